// round 17
// baseline (speedup 1.0000x reference)
#include <cuda_runtime.h>
#include <cuda_bf16.h>
#include <cuda_fp16.h>
#include <stdint.h>

// ============================================================================
// AllegroLayer edge-MLP (sm_103a).
//
// tcgen05 path (arch-specific pass) + fp32 f32x2 fallback (plain compute_103).
//
// R17:
//  - proj gather made COALESCED: warpgroup cooperatively stages all 256
//    fp16 proj half-rows into the (dead-after-A-copy) x-buffer (4 lines per
//    warp instr instead of 32); epilogue 1 reads via conflict-free LDS.
//  - residual x re-read fp32 cooperatively during layer-3 MMA window
//    (L2-resident); final epilogue uses exact fp32 x (no hi+lo reconstruct).
//  - (kept) 3 wg pipelines, convert-at-staging, fp16 proj, fp16 h for
//    layers 2/3, SMEM-bounce coalesced output, int32 indexing.
// ============================================================================

#if defined(__CUDA_ARCH_FEAT_SM103_ALL) || \
    (defined(__CUDA_ARCH_SPECIFIC__) && defined(__CUDA_ARCH__) && (__CUDA_ARCH__ == 1030))
#define HAS_TC 1
#else
#define HAS_TC 0
#endif

#define N_NODES_MAX 50048
#define TILE 128
#define IDESC_BF 0x8100490u   // kind::f16: F32 acc, BF16 a/b, N=64, M=128
#define IDESC_FP 0x8100010u   // kind::f16: F32 acc, F16 a/b,  N=64, M=128

__device__ __half g_projh[(size_t)N_NODES_MAX * 128];
__device__ int g_is64;
__device__ __align__(16) unsigned char g_wimg[65536];

#define WI_B1H 0
#define WI_B1L 16384
#define WI_B2H 32768
#define WI_B2L 40960
#define WI_B3H 49152
#define WI_B3L 57344

// SMEM layout (bytes)
#define SM_W     0
#define XROW_U32 84            // bf16 hi/lo staging stride (conflict-free)
#define PROW_U32 36            // proj overlay stride (36 mod 32 = 4, CF)
#define FROW_U32 68            // fp32 x / y overlay stride (68 mod 32 = 4, CF)
#define XBUF_B   (TILE * XROW_U32 * 4)       // 43008 (>= overlays: 36864, 34816)
#define SM_XS    65536
#define XS_OFF(wg) (SM_XS + (wg) * XBUF_B)
#define SM_VEC   (SM_XS + 3 * XBUF_B)
#define SM_B1V   SM_VEC
#define SM_B2V   (SM_VEC + 256)
#define SM_B3V   (SM_VEC + 512)
#define SM_GV    (SM_VEC + 768)
#define SM_BTV   (SM_VEC + 1024)
#define SM_PTR   (SM_VEC + 1280)
#define SM_MBAR  (SM_VEC + 1288)
#define SM_IDX   (SM_VEC + 1312)             // 3 wg x 256 ints = 3072 B
#define SMEM_BYTES (SM_IDX + 3072)           // 198944

// fallback fp32 weights (floats, within SM_W)
#define FB_W1E  0
#define FB_W1R  (64 * 64)
#define FB_W2   (FB_W1R + 16 * 64)
#define FB_W3   (FB_W2 + 64 * 64)

// TMEM per-wg slot (base = wg*160)
#define TM_SLOT 160
#define TM_AHI 0
#define TM_ALO 48
#define TM_D   96

typedef unsigned long long ull;

// ---------------------------------------------------------------------------
__device__ __forceinline__ uint32_t smem_u32(const void* p) {
    uint32_t a;
    asm("{ .reg .u64 t; cvta.to.shared.u64 t, %1; cvt.u32.u64 %0, t; }"
        : "=r"(a) : "l"(p));
    return a;
}
__device__ __forceinline__ uint32_t pkbf(float a, float b) {
    __nv_bfloat162 t = __floats2bfloat162_rn(a, b);
    return *(uint32_t*)&t;
}
__device__ __forceinline__ uint32_t pkh(float a, float b) {
    __half2 t = __floats2half2_rn(a, b);
    return *(uint32_t*)&t;
}
__device__ __forceinline__ float2 upbf(uint32_t p) {
    __nv_bfloat162 h = *(__nv_bfloat162*)&p;
    return make_float2(__bfloat162float(h.x), __bfloat162float(h.y));
}
__device__ __forceinline__ float2 uph(uint32_t p) {
    __half2 h = *(__half2*)&p;
    return __half22float2(h);
}
__device__ __forceinline__ float silu_f(float x) {
    float h = 0.5f * x, t;
    asm("tanh.approx.f32 %0, %1;" : "=f"(t) : "f"(h));
    return h + h * t;
}
__device__ __forceinline__ ull pk2(float lo, float hi) {
    ull r;
    asm("mov.b64 %0, {%1, %2};" : "=l"(r) : "f"(lo), "f"(hi));
    return r;
}
__device__ __forceinline__ void upk2(ull v, float& lo, float& hi) {
    asm("mov.b64 {%0, %1}, %2;" : "=f"(lo), "=f"(hi) : "l"(v));
}
__device__ __forceinline__ void fma2(ull& d, ull a, ull b) {
    asm("fma.rn.f32x2 %0, %1, %2, %0;" : "+l"(d) : "l"(a), "l"(b));
}
#define PF_L2(p) asm volatile("prefetch.global.L2 [%0];" :: "l"(p))
#define WG_BAR(wg) asm volatile("bar.sync %0, 128;" :: "r"((wg) + 1) : "memory")

#if HAS_TC
__device__ __forceinline__ uint32_t elect_one() {
    uint32_t p;
    asm volatile("{\n\t.reg .pred p;\n\telect.sync _|p, 0xFFFFFFFF;\n\t"
                 "selp.b32 %0, 1, 0, p;\n\t}" : "=r"(p));
    return p;
}
__device__ __forceinline__ uint64_t mkdesc(uint32_t addr) {
    return ((uint64_t)2 << 61) | ((uint64_t)1 << 46) | ((uint64_t)64 << 32) |
           ((uint64_t)1 << 16) | ((addr >> 4) & 0x3FFF);
}
#define TC_ALLOC(sa, n) \
    asm volatile("tcgen05.alloc.cta_group::1.sync.aligned.shared::cta.b32 [%0], %1;" \
                 :: "r"(sa), "r"((uint32_t)(n)) : "memory")
#define TC_RELINQ() \
    asm volatile("tcgen05.relinquish_alloc_permit.cta_group::1.sync.aligned;")
#define TC_DEALLOC(t, n) \
    asm volatile("tcgen05.dealloc.cta_group::1.sync.aligned.b32 %0, %1;" :: "r"(t), "r"((uint32_t)(n)))
#define TC_COMMIT(mb) \
    asm volatile("tcgen05.commit.cta_group::1.mbarrier::arrive::one.shared::cluster.b64 [%0];" \
                 :: "r"(mb) : "memory")
#define TC_WAIT_ST() asm volatile("tcgen05.wait::st.sync.aligned;" ::: "memory")
#define TC_WAIT_LD() asm volatile("tcgen05.wait::ld.sync.aligned;" ::: "memory")
#define TC_FENCE_BEFORE() asm volatile("tcgen05.fence::before_thread_sync;" ::: "memory")
#define TC_FENCE_AFTER()  asm volatile("tcgen05.fence::after_thread_sync;" ::: "memory")
#define MB_INIT(mb, c) \
    asm volatile("mbarrier.init.shared.b64 [%0], %1;" :: "r"(mb), "r"((uint32_t)(c)) : "memory")
#define MB_WAIT(mb, par) do { \
    uint32_t _m = (mb), _p = (par), _d; \
    asm volatile("{\n\t.reg .pred p;\n\t" \
        "mbarrier.try_wait.parity.acquire.cta.shared::cta.b64 p, [%1], %2;\n\t" \
        "selp.b32 %0, 1, 0, p;\n\t}" : "=r"(_d) : "r"(_m), "r"(_p) : "memory"); \
    if (!_d) { \
        asm volatile("{\n\t.reg .pred P1;\n\tWL_%=:\n\t" \
            "mbarrier.try_wait.parity.acquire.cta.shared::cta.b64 P1, [%0], %1, 0x989680;\n\t" \
            "@P1 bra.uni WD_%=;\n\tbra.uni WL_%=;\n\tWD_%=:\n\t}" \
            :: "r"(_m), "r"(_p) : "memory"); \
    } } while (0)

#define TMST_X16(addr, r) \
    asm volatile("tcgen05.st.sync.aligned.32x32b.x16.b32 [%0], " \
        "{%1,%2,%3,%4,%5,%6,%7,%8,%9,%10,%11,%12,%13,%14,%15,%16};" \
        :: "r"(addr), \
        "r"((r)[0]),"r"((r)[1]),"r"((r)[2]),"r"((r)[3]),"r"((r)[4]),"r"((r)[5]),"r"((r)[6]),"r"((r)[7]), \
        "r"((r)[8]),"r"((r)[9]),"r"((r)[10]),"r"((r)[11]),"r"((r)[12]),"r"((r)[13]),"r"((r)[14]),"r"((r)[15]) \
        : "memory")
#define TMST_X8(addr, r) \
    asm volatile("tcgen05.st.sync.aligned.32x32b.x8.b32 [%0], " \
        "{%1,%2,%3,%4,%5,%6,%7,%8};" \
        :: "r"(addr), \
        "r"((r)[0]),"r"((r)[1]),"r"((r)[2]),"r"((r)[3]),"r"((r)[4]),"r"((r)[5]),"r"((r)[6]),"r"((r)[7]) \
        : "memory")
#define TMLD_X32(r, addr) \
    asm volatile("tcgen05.ld.sync.aligned.32x32b.x32.b32 " \
        "{%0,%1,%2,%3,%4,%5,%6,%7,%8,%9,%10,%11,%12,%13,%14,%15," \
        "%16,%17,%18,%19,%20,%21,%22,%23,%24,%25,%26,%27,%28,%29,%30,%31}, [%32];" \
        : "=r"((r)[0]),"=r"((r)[1]),"=r"((r)[2]),"=r"((r)[3]),"=r"((r)[4]),"=r"((r)[5]),"=r"((r)[6]),"=r"((r)[7]), \
          "=r"((r)[8]),"=r"((r)[9]),"=r"((r)[10]),"=r"((r)[11]),"=r"((r)[12]),"=r"((r)[13]),"=r"((r)[14]),"=r"((r)[15]), \
          "=r"((r)[16]),"=r"((r)[17]),"=r"((r)[18]),"=r"((r)[19]),"=r"((r)[20]),"=r"((r)[21]),"=r"((r)[22]),"=r"((r)[23]), \
          "=r"((r)[24]),"=r"((r)[25]),"=r"((r)[26]),"=r"((r)[27]),"=r"((r)[28]),"=r"((r)[29]),"=r"((r)[30]),"=r"((r)[31]) \
        : "r"(addr))

__device__ __forceinline__ void mma_ts(uint32_t d, uint32_t a, uint64_t bd,
                                       uint32_t idesc, uint32_t en) {
    asm volatile("{\n\t.reg .pred p;\n\tsetp.ne.u32 p, %5, 0;\n\t"
                 "tcgen05.mma.cta_group::1.kind::f16 [%0], [%1], %2, %3, "
                 "{%4, %4, %4, %4}, p;\n\t}"
                 :: "r"(d), "r"(a), "l"(bd), "r"(idesc), "r"(0u), "r"(en)
                 : "memory");
}
#endif  // HAS_TC

// ---------------------------------------------------------------------------
__global__ void detect_idx_kernel(const unsigned int* __restrict__ w) {
    unsigned int acc = 0;
#pragma unroll
    for (int i = 1; i < 256; i += 2) acc |= w[i];
    g_is64 = (acc == 0) ? 1 : 0;
}

// ---------------------------------------------------------------------------
__global__ void prep_w_kernel(const float* __restrict__ W1,
                              const float* __restrict__ W2,
                              const float* __restrict__ W3) {
    int stride = blockDim.x * gridDim.x;
    int t0 = blockIdx.x * blockDim.x + threadIdx.x;
    for (int i = t0; i < 64 * 128; i += stride) {
        int n = i >> 7, k = i & 127;
        float w = 0.f;
        if (k < 64) w = W1[k * 64 + n];
        else if (k < 80) w = W1[(192 + k - 64) * 64 + n];
        uint32_t bo = ((uint32_t)(n >> 3) + ((uint32_t)(k * 2) >> 7) * 8u) * 1024u
                    + (uint32_t)(n & 7) * 128u + ((uint32_t)(k * 2) & 127u);
        uint32_t sw = bo ^ ((bo >> 3) & 0x70);
        __nv_bfloat16 hi = __float2bfloat16(w);
        __nv_bfloat16 lo = __float2bfloat16(w - __bfloat162float(hi));
        *(__nv_bfloat16*)(g_wimg + WI_B1H + sw) = hi;
        *(__nv_bfloat16*)(g_wimg + WI_B1L + sw) = lo;
    }
    for (int i = t0; i < 64 * 64; i += stride) {
        int n = i >> 6, k = i & 63;
        uint32_t bo = (uint32_t)(n >> 3) * 1024u + (uint32_t)(n & 7) * 128u
                    + (uint32_t)(k * 2);
        uint32_t sw = bo ^ ((bo >> 3) & 0x70);
        float w2 = W2[k * 64 + n];
        __half h2 = __float2half_rn(w2);
        *(__half*)(g_wimg + WI_B2H + sw) = h2;
        *(__half*)(g_wimg + WI_B2L + sw) = __float2half_rn(w2 - __half2float(h2));
        float w3 = W3[k * 64 + n];
        __half h3 = __float2half_rn(w3);
        *(__half*)(g_wimg + WI_B3H + sw) = h3;
        *(__half*)(g_wimg + WI_B3L + sw) = __float2half_rn(w3 - __half2float(h3));
    }
}

// ---------------------------------------------------------------------------
// Kernel A: per-node projections (fp32 compute, fp16 storage)
// ---------------------------------------------------------------------------
__global__ void __launch_bounds__(256) node_proj_kernel(
    const float* __restrict__ nf, const float* __restrict__ W1, int N)
{
    __shared__ float Wn[64 * 128];
    __shared__ float nfs[16 * 65];
    int tid = threadIdx.x;
    for (int i = tid; i < 64 * 128; i += 256) {
        int d = i >> 7, jj = i & 127;
        Wn[i] = (jj < 64) ? W1[(64 + d) * 64 + jj]
                          : W1[(128 + d) * 64 + (jj - 64)];
    }
    int n0 = blockIdx.x * 16;
    for (int i = tid; i < 16 * 64; i += 256) {
        int nl = i >> 6, d = i & 63;
        int n = n0 + nl;
        nfs[nl * 65 + d] = (n < N) ? nf[(size_t)n * 64 + d] : 0.f;
    }
    __syncthreads();
    int nl = tid & 15;
    int j0 = (tid >> 4) * 8;
    float acc[8] = {0.f, 0.f, 0.f, 0.f, 0.f, 0.f, 0.f, 0.f};
#pragma unroll 4
    for (int d = 0; d < 64; ++d) {
        float v = nfs[nl * 65 + d];
        const float4* w = (const float4*)(Wn + d * 128 + j0);
        float4 w0 = w[0], w1 = w[1];
        acc[0] += v * w0.x; acc[1] += v * w0.y; acc[2] += v * w0.z; acc[3] += v * w0.w;
        acc[4] += v * w1.x; acc[5] += v * w1.y; acc[6] += v * w1.z; acc[7] += v * w1.w;
    }
    int n = n0 + nl;
    if (n < N) {
        uint4 u;
        u.x = pkh(acc[0], acc[1]); u.y = pkh(acc[2], acc[3]);
        u.z = pkh(acc[4], acc[5]); u.w = pkh(acc[6], acc[7]);
        *(uint4*)(g_projh + (size_t)n * 128 + j0) = u;
    }
}

// fallback per-thread GEMM K-step
__device__ __forceinline__ void gemm_step(ull* acc, float xk, const float* wrow) {
    ull xk2 = pk2(xk, xk);
    const ulonglong2* w = (const ulonglong2*)wrow;
#pragma unroll
    for (int m = 0; m < 16; ++m) {
        ulonglong2 ww = w[m];
        fma2(acc[2 * m],     xk2, ww.x);
        fma2(acc[2 * m + 1], xk2, ww.y);
    }
}

__device__ __forceinline__ void load_idx(const void* eidx_raw, int is64,
                                         int E, int eld,
                                         int& nrow, int& ncol) {
    long long r, c;
    if (is64) {
        const long long* p = (const long long*)eidx_raw;
        r = p[eld]; c = p[E + eld];
    } else {
        const int* p = (const int*)eidx_raw;
        r = p[eld]; c = p[E + eld];
    }
    if (r < 0) r = 0; if (r >= N_NODES_MAX) r = N_NODES_MAX - 1;
    if (c < 0) c = 0; if (c >= N_NODES_MAX) c = N_NODES_MAX - 1;
    nrow = (int)r; ncol = (int)c;
}

#if HAS_TC
// stage one tile: coalesced float4 loads, convert to hi/lo bf16x2, SMEM store
__device__ __forceinline__ void stage_tile_tc(
    uint32_t* __restrict__ xs, const float* __restrict__ ef,
    const float* __restrict__ rbf, int base, int E, int wg_tid)
{
#pragma unroll 4
    for (int i = wg_tid; i < TILE * 16; i += 128) {
        int r = i >> 4, q = i & 15;
        int e = base + r; if (e >= E) e = E - 1;
        float4 v = ((const float4*)ef)[(size_t)e * 16 + q];
        uint32_t h0 = pkbf(v.x, v.y), h1 = pkbf(v.z, v.w);
        float2 f0 = upbf(h0), f1 = upbf(h1);
        uint32_t l0 = pkbf(v.x - f0.x, v.y - f0.y);
        uint32_t l1 = pkbf(v.z - f1.x, v.w - f1.y);
        *(uint2*)&xs[r * XROW_U32 + 2 * q]      = make_uint2(h0, h1);
        *(uint2*)&xs[r * XROW_U32 + 40 + 2 * q] = make_uint2(l0, l1);
    }
#pragma unroll
    for (int i = wg_tid; i < TILE * 4; i += 128) {
        int r = i >> 2, q = i & 3;
        int e = base + r; if (e >= E) e = E - 1;
        float4 v = ((const float4*)rbf)[(size_t)e * 4 + q];
        uint32_t h0 = pkbf(v.x, v.y), h1 = pkbf(v.z, v.w);
        float2 f0 = upbf(h0), f1 = upbf(h1);
        uint32_t l0 = pkbf(v.x - f0.x, v.y - f0.y);
        uint32_t l1 = pkbf(v.z - f1.x, v.w - f1.y);
        *(uint2*)&xs[r * XROW_U32 + 32 + 2 * q] = make_uint2(h0, h1);
        *(uint2*)&xs[r * XROW_U32 + 72 + 2 * q] = make_uint2(l0, l1);
    }
}
#endif

// ---------------------------------------------------------------------------
// Kernel B: persistent edge MLP. 384 threads = 3 warpgroup pipelines.
// ---------------------------------------------------------------------------
__global__ void __launch_bounds__(384) edge_tc_kernel(
    const float* __restrict__ ef, const void* __restrict__ eidx_raw,
    const float* __restrict__ rbf,
    const float* __restrict__ W1, const float* __restrict__ W2,
    const float* __restrict__ W3,
    const float* __restrict__ b1, const float* __restrict__ b2,
    const float* __restrict__ b3, const float* __restrict__ gamma,
    const float* __restrict__ beta, float* __restrict__ out,
    int E, int ntiles)
{
    extern __shared__ __align__(1024) unsigned char smraw[];
    float* smf = (float*)smraw;
    int tid = threadIdx.x;
    int wg = tid >> 7;
    int wg_tid = tid & 127;
    int warp_in_wg = (tid >> 5) & 3;
    int is64 = g_is64;
    int pipes = gridDim.x * 3;

    if (tid < 64) {
        smf[SM_B1V / 4 + tid] = b1[tid];
        smf[SM_B2V / 4 + tid] = b2[tid];
        smf[SM_B3V / 4 + tid] = b3[tid];
        smf[SM_GV / 4 + tid]  = gamma[tid];
        smf[SM_BTV / 4 + tid] = beta[tid];
    }

#if HAS_TC
    uint32_t smb = smem_u32(smraw);
    {
        const float4* src = (const float4*)g_wimg;
        float4* dst = (float4*)(smraw + SM_W);
        for (int i = tid; i < 65536 / 16; i += 384) dst[i] = src[i];
    }
    if (tid == 0) {
        MB_INIT(smb + SM_MBAR, 1);
        MB_INIT(smb + SM_MBAR + 8, 1);
        MB_INIT(smb + SM_MBAR + 16, 1);
    }
    if ((tid >> 5) == 0) {
        TC_ALLOC(smb + SM_PTR, 512);
        TC_RELINQ();   // persistent CTA must not hold the alloc permit
    }
    __syncthreads();
    uint32_t tm;
    asm("ld.shared.b32 %0, [%1];" : "=r"(tm) : "r"(smb + SM_PTR));
    uint32_t ts = tm + (uint32_t)wg * TM_SLOT;
    uint32_t wo = (uint32_t)warp_in_wg << 21;
    uint32_t mb = smb + SM_MBAR + (uint32_t)wg * 8;

    uint64_t d_b1h = mkdesc(smb + SM_W + WI_B1H);
    uint64_t d_b1l = mkdesc(smb + SM_W + WI_B1L);
    uint64_t d_b2h = mkdesc(smb + SM_W + WI_B2H);
    uint64_t d_b2l = mkdesc(smb + SM_W + WI_B2L);
    uint64_t d_b3h = mkdesc(smb + SM_W + WI_B3H);
    uint64_t d_b3l = mkdesc(smb + SM_W + WI_B3L);
    uint32_t ph = 0;

    uint32_t* xs = (uint32_t*)(smraw + XS_OFF(wg));
    float* xsf = (float*)xs;
    const uint32_t* xrow = xs + wg_tid * XROW_U32;
    int* sidx = (int*)(smraw + SM_IDX) + wg * 256;   // [0:128) row, [128:256) col

    int t = blockIdx.x * 3 + wg;

    if (t < ntiles) {
        int base = t * TILE;
        stage_tile_tc(xs, ef, rbf, base, E, wg_tid);
        int e0 = base + wg_tid; if (e0 >= E) e0 = E - 1;
        int nr, nc;
        load_idx(eidx_raw, is64, E, e0, nr, nc);
        sidx[wg_tid] = nr; sidx[128 + wg_tid] = nc;
        PF_L2(g_projh + (size_t)nr * 128);
        PF_L2(g_projh + (size_t)nc * 128 + 64);
    }

    for (; t < ntiles; t += pipes) {
        int base = t * TILE;
        int e = base + wg_tid;

        WG_BAR(wg);   // staged buffer + sidx visible

        // ---- A to TMEM: straight copy of pre-packed hi/lo words ----
        {
            uint32_t v[16];
            const uint4* rq = (const uint4*)xrow;
#pragma unroll
            for (int j = 0; j < 4; ++j) *(uint4*)&v[4 * j] = rq[j];
            TMST_X16(ts + TM_AHI + wo, v);
#pragma unroll
            for (int j = 0; j < 4; ++j) *(uint4*)&v[4 * j] = rq[4 + j];
            TMST_X16(ts + TM_AHI + 16 + wo, v);
#pragma unroll
            for (int j = 0; j < 2; ++j) *(uint4*)&v[4 * j] = rq[8 + j];
            TMST_X8(ts + TM_AHI + 32 + wo, v);
#pragma unroll
            for (int j = 0; j < 4; ++j) *(uint4*)&v[4 * j] = rq[10 + j];
            TMST_X16(ts + TM_ALO + wo, v);
#pragma unroll
            for (int j = 0; j < 4; ++j) *(uint4*)&v[4 * j] = rq[14 + j];
            TMST_X16(ts + TM_ALO + 16 + wo, v);
#pragma unroll
            for (int j = 0; j < 2; ++j) *(uint4*)&v[4 * j] = rq[18 + j];
            TMST_X8(ts + TM_ALO + 32 + wo, v);
        }
        TC_WAIT_ST();
        TC_FENCE_BEFORE();
        WG_BAR(wg);   // all A reads done -> x-buffer is now dead, reusable

        // ---- layer 1 MMAs: 3 terms x 5 K-steps (K=80), split bf16 ----
        if (warp_in_wg == 0 && elect_one()) {
            TC_FENCE_AFTER();
            const int doff1[5] = {0, 2, 4, 6, 512};
#pragma unroll
            for (int s = 0; s < 5; ++s)
                mma_ts(ts + TM_D, ts + TM_AHI + s * 8, d_b1h + doff1[s], IDESC_BF, s > 0);
#pragma unroll
            for (int s = 0; s < 5; ++s)
                mma_ts(ts + TM_D, ts + TM_ALO + s * 8, d_b1h + doff1[s], IDESC_BF, 1);
#pragma unroll
            for (int s = 0; s < 5; ++s)
                mma_ts(ts + TM_D, ts + TM_AHI + s * 8, d_b1l + doff1[s], IDESC_BF, 1);
            TC_COMMIT(mb);
        }

        // ---- cooperative COALESCED proj gather into x-buffer overlay ----
        // proj-i rows at xs[r*36], proj-j rows at xs[4608 + r*36] (u32).
        {
            int sub = wg_tid >> 3, ch = wg_tid & 7;
#pragma unroll
            for (int it = 0; it < 8; ++it) {
                int r = it * 16 + sub;
                uint4 vi = *(const uint4*)(g_projh + (size_t)sidx[r] * 128 + ch * 8);
                uint4 vj = *(const uint4*)(g_projh + (size_t)sidx[128 + r] * 128 + 64 + ch * 8);
                *(uint4*)&xs[r * PROW_U32 + ch * 4] = vi;
                *(uint4*)&xs[128 * PROW_U32 + r * PROW_U32 + ch * 4] = vj;
            }
        }
        WG_BAR(wg);   // proj staged; sidx reads done

        // ---- next tile's indices -> sidx + L2 prefetch ----
        int tn = t + pipes;
        if (tn < ntiles) {
            int en0 = tn * TILE + wg_tid; if (en0 >= E) en0 = E - 1;
            int nr, nc;
            load_idx(eidx_raw, is64, E, en0, nr, nc);
            sidx[wg_tid] = nr; sidx[128 + wg_tid] = nc;
            PF_L2(g_projh + (size_t)nr * 128);
            PF_L2(g_projh + (size_t)nc * 128 + 64);
        }

        MB_WAIT(mb, ph); ph ^= 1;
        TC_FENCE_AFTER();

        // ---- epilogue 1: h = silu(d + b1 + proj_i + proj_j) -> fp16 ----
        {
            const uint4* pi4 = (const uint4*)&xs[wg_tid * PROW_U32];
            const uint4* pj4 = (const uint4*)&xs[128 * PROW_U32 + wg_tid * PROW_U32];
            const float4* Bv = (const float4*)(smraw + SM_B1V);
#pragma unroll
            for (int half = 0; half < 2; ++half) {
                uint32_t dr[32];
                TMLD_X32(dr, ts + TM_D + half * 32 + wo);
                uint32_t wi[16], wj[16];
#pragma unroll
                for (int j = 0; j < 4; ++j) {
                    *(uint4*)&wi[4 * j] = pi4[4 * half + j];
                    *(uint4*)&wj[4 * j] = pj4[4 * half + j];
                }
                TC_WAIT_LD();
                uint32_t hh[16];
#pragma unroll
                for (int q = 0; q < 8; ++q) {
                    int qq = half * 8 + q;
                    float2 piA = uph(wi[2 * q]), piB = uph(wi[2 * q + 1]);
                    float2 pjA = uph(wj[2 * q]), pjB = uph(wj[2 * q + 1]);
                    float4 bb = Bv[qq];
                    float v0 = silu_f(__uint_as_float(dr[4 * q + 0]) + bb.x + piA.x + pjA.x);
                    float v1 = silu_f(__uint_as_float(dr[4 * q + 1]) + bb.y + piA.y + pjA.y);
                    float v2 = silu_f(__uint_as_float(dr[4 * q + 2]) + bb.z + piB.x + pjB.x);
                    float v3 = silu_f(__uint_as_float(dr[4 * q + 3]) + bb.w + piB.y + pjB.y);
                    hh[2 * q]     = pkh(v0, v1);
                    hh[2 * q + 1] = pkh(v2, v3);
                }
                TMST_X16(ts + TM_AHI + half * 16 + wo, hh);
            }
        }
        TC_WAIT_ST();
        TC_FENCE_BEFORE();
        WG_BAR(wg);   // epi1 done -> proj overlay dead

        // ---- layer 2 MMAs: 2 terms x 4 K-steps (fp16) ----
        if (warp_in_wg == 0 && elect_one()) {
            TC_FENCE_AFTER();
#pragma unroll
            for (int s = 0; s < 4; ++s)
                mma_ts(ts + TM_D, ts + TM_AHI + s * 8, d_b2h + s * 2, IDESC_FP, s > 0);
#pragma unroll
            for (int s = 0; s < 4; ++s)
                mma_ts(ts + TM_D, ts + TM_AHI + s * 8, d_b2l + s * 2, IDESC_FP, 1);
            TC_COMMIT(mb);
        }
        MB_WAIT(mb, ph); ph ^= 1;
        TC_FENCE_AFTER();

        // ---- epilogue 2: h = silu(d + b2) -> fp16 ----
        {
            const float4* Bv = (const float4*)(smraw + SM_B2V);
#pragma unroll
            for (int half = 0; half < 2; ++half) {
                uint32_t dr[32];
                TMLD_X32(dr, ts + TM_D + half * 32 + wo);
                TC_WAIT_LD();
                uint32_t hh[16];
#pragma unroll
                for (int q = 0; q < 8; ++q) {
                    int qq = half * 8 + q;
                    float4 bb = Bv[qq];
                    float v0 = silu_f(__uint_as_float(dr[4 * q + 0]) + bb.x);
                    float v1 = silu_f(__uint_as_float(dr[4 * q + 1]) + bb.y);
                    float v2 = silu_f(__uint_as_float(dr[4 * q + 2]) + bb.z);
                    float v3 = silu_f(__uint_as_float(dr[4 * q + 3]) + bb.w);
                    hh[2 * q]     = pkh(v0, v1);
                    hh[2 * q + 1] = pkh(v2, v3);
                }
                TMST_X16(ts + TM_AHI + half * 16 + wo, hh);
            }
        }
        TC_WAIT_ST();
        TC_FENCE_BEFORE();
        WG_BAR(wg);

        // ---- layer 3 MMAs: 2 terms x 4 K-steps (fp16) ----
        if (warp_in_wg == 0 && elect_one()) {
            TC_FENCE_AFTER();
#pragma unroll
            for (int s = 0; s < 4; ++s)
                mma_ts(ts + TM_D, ts + TM_AHI + s * 8, d_b3h + s * 2, IDESC_FP, s > 0);
#pragma unroll
            for (int s = 0; s < 4; ++s)
                mma_ts(ts + TM_D, ts + TM_AHI + s * 8, d_b3l + s * 2, IDESC_FP, 1);
            TC_COMMIT(mb);
        }

        // ---- cooperative fp32 x re-read (L2-resident) into stride-68 ----
#pragma unroll 4
        for (int i = wg_tid; i < TILE * 16; i += 128) {
            int r = i >> 4, q = i & 15;
            int e2 = base + r; if (e2 >= E) e2 = E - 1;
            *(float4*)&xsf[r * FROW_U32 + 4 * q] = ((const float4*)ef)[(size_t)e2 * 16 + q];
        }
        WG_BAR(wg);   // x fp32 staged

        MB_WAIT(mb, ph); ph ^= 1;
        TC_FENCE_AFTER();

        // ---- final: y = x + d + b3; LayerNorm; y into same rows; STG ----
        {
            const float4* Bv = (const float4*)(smraw + SM_B3V);
            const float4* xf = (const float4*)&xsf[wg_tid * FROW_U32];
            float y[64];
            float s1 = 0.f, s2 = 0.f;
#pragma unroll
            for (int half = 0; half < 2; ++half) {
                uint32_t dr[32];
                TMLD_X32(dr, ts + TM_D + half * 32 + wo);
                TC_WAIT_LD();
#pragma unroll
                for (int j = 0; j < 8; ++j) {
                    float4 xv = xf[half * 8 + j];
                    int o0 = half * 32 + 4 * j;
                    float4 bb = Bv[o0 >> 2];
                    float v0 = xv.x + __uint_as_float(dr[4 * j + 0]) + bb.x;
                    float v1 = xv.y + __uint_as_float(dr[4 * j + 1]) + bb.y;
                    float v2 = xv.z + __uint_as_float(dr[4 * j + 2]) + bb.z;
                    float v3 = xv.w + __uint_as_float(dr[4 * j + 3]) + bb.w;
                    y[o0] = v0; y[o0 + 1] = v1; y[o0 + 2] = v2; y[o0 + 3] = v3;
                    s1 += v0 + v1 + v2 + v3;
                    s2 += v0 * v0 + v1 * v1 + v2 * v2 + v3 * v3;
                }
            }
            float mu  = s1 * (1.f / 64.f);
            float var = s2 * (1.f / 64.f) - mu * mu;
            float inv = rsqrtf(var + 1e-5f);
            {
                const float4* Gv = (const float4*)(smraw + SM_GV);
                const float4* Tv = (const float4*)(smraw + SM_BTV);
                float4* yrow = (float4*)&xsf[wg_tid * FROW_U32];
#pragma unroll
                for (int q = 0; q < 16; ++q) {
                    float4 g4 = Gv[q], t4 = Tv[q], r4;
                    r4.x = (y[4 * q + 0] - mu) * inv * g4.x + t4.x;
                    r4.y = (y[4 * q + 1] - mu) * inv * g4.y + t4.y;
                    r4.z = (y[4 * q + 2] - mu) * inv * g4.z + t4.z;
                    r4.w = (y[4 * q + 3] - mu) * inv * g4.w + t4.w;
                    yrow[q] = r4;
                }
            }
        }
        WG_BAR(wg);   // all y rows in SMEM

        // ---- coalesced output store ----
#pragma unroll 4
        for (int i = wg_tid; i < TILE * 16; i += 128) {
            int r = i >> 4, q = i & 15;
            int eo = base + r;
            if (eo < E)
                ((float4*)out)[(size_t)eo * 16 + q] = *(const float4*)&xsf[r * FROW_U32 + 4 * q];
        }

        WG_BAR(wg);   // buffer free before restage

        if (tn < ntiles)
            stage_tile_tc(xs, ef, rbf, tn * TILE, E, wg_tid);
    }
    __syncthreads();
    if ((tid >> 5) == 0) TC_DEALLOC(tm, 512);

#else  // ================= fp32 f32x2 fallback (non-arch-specific pass) =====

    float* wsm = smf + SM_W / 4;
    for (int i = tid; i < 64 * 64; i += 384) wsm[FB_W1E + i] = W1[i];
    for (int i = tid; i < 16 * 64; i += 384) wsm[FB_W1R + i] = W1[192 * 64 + i];
    for (int i = tid; i < 64 * 64; i += 384) wsm[FB_W2 + i] = W2[i];
    for (int i = tid; i < 64 * 64; i += 384) wsm[FB_W3 + i] = W3[i];
    __syncthreads();

    float* xs = (float*)(smraw + XS_OFF(wg));
    for (int t = blockIdx.x * 3 + wg; t < ntiles; t += pipes) {
        int base = t * TILE;
        WG_BAR(wg);
        for (int i = wg_tid; i < TILE * 16; i += 128) {
            int r = i >> 4, q = i & 15;
            int e = base + r; if (e >= E) e = E - 1;
            *(float4*)&xs[r * XROW_U32 + q * 4] = ((const float4*)ef)[(size_t)e * 16 + q];
        }
        for (int i = wg_tid; i < TILE * 4; i += 128) {
            int r = i >> 2, q = i & 3;
            int e = base + r; if (e >= E) e = E - 1;
            *(float4*)&xs[r * XROW_U32 + 64 + q * 4] = ((const float4*)rbf)[(size_t)e * 4 + q];
        }
        WG_BAR(wg);

        int e = base + wg_tid;
        int eld = (e < E) ? e : (E - 1);
        int nrow, ncol;
        load_idx(eidx_raw, is64, E, eld, nrow, ncol);

        const __half2* pIh = (const __half2*)(g_projh + (size_t)nrow * 128);
        const __half2* pJh = (const __half2*)(g_projh + (size_t)ncol * 128 + 64);
        const float* xr = xs + wg_tid * XROW_U32;

        ull acc[32];
#pragma unroll
        for (int m = 0; m < 16; ++m) {
            float4 bb = ((const float4*)(smraw + SM_B1V))[m];
            float2 a01 = __half22float2(pIh[2 * m]);
            float2 a23 = __half22float2(pIh[2 * m + 1]);
            float2 b01 = __half22float2(pJh[2 * m]);
            float2 b23 = __half22float2(pJh[2 * m + 1]);
            acc[2 * m]     = pk2(bb.x + a01.x + b01.x, bb.y + a01.y + b01.y);
            acc[2 * m + 1] = pk2(bb.z + a23.x + b23.x, bb.w + a23.y + b23.y);
        }
#pragma unroll
        for (int k = 0; k < 64; ++k) gemm_step(acc, xr[k], wsm + FB_W1E + k * 64);
#pragma unroll
        for (int k = 0; k < 16; ++k) gemm_step(acc, xr[64 + k], wsm + FB_W1R + k * 64);

        float h[64];
#pragma unroll
        for (int p = 0; p < 32; ++p) {
            float a, b; upk2(acc[p], a, b);
            h[2 * p] = silu_f(a); h[2 * p + 1] = silu_f(b);
        }
#pragma unroll
        for (int m = 0; m < 16; ++m) {
            float4 bb = ((const float4*)(smraw + SM_B2V))[m];
            acc[2 * m] = pk2(bb.x, bb.y); acc[2 * m + 1] = pk2(bb.z, bb.w);
        }
#pragma unroll
        for (int k = 0; k < 64; ++k) gemm_step(acc, h[k], wsm + FB_W2 + k * 64);
#pragma unroll
        for (int p = 0; p < 32; ++p) {
            float a, b; upk2(acc[p], a, b);
            h[2 * p] = silu_f(a); h[2 * p + 1] = silu_f(b);
        }
#pragma unroll
        for (int m = 0; m < 16; ++m) {
            float4 bb = ((const float4*)(smraw + SM_B3V))[m];
            acc[2 * m] = pk2(bb.x, bb.y); acc[2 * m + 1] = pk2(bb.z, bb.w);
        }
#pragma unroll
        for (int k = 0; k < 64; ++k) gemm_step(acc, h[k], wsm + FB_W3 + k * 64);

        float y[64];
        float s1 = 0.f, s2 = 0.f;
#pragma unroll
        for (int p = 0; p < 32; ++p) {
            float a, b; upk2(acc[p], a, b);
            float ya = xr[2 * p] + a, yb = xr[2 * p + 1] + b;
            y[2 * p] = ya; y[2 * p + 1] = yb;
            s1 += ya + yb; s2 += ya * ya + yb * yb;
        }
        float mu  = s1 * (1.f / 64.f);
        float var = s2 * (1.f / 64.f) - mu * mu;
        float inv = rsqrtf(var + 1e-5f);
        if (e < E) {
            float4* o = (float4*)(out + (size_t)e * 64);
#pragma unroll
            for (int q = 0; q < 16; ++q) {
                float4 g4 = ((const float4*)(smraw + SM_GV))[q];
                float4 t4 = ((const float4*)(smraw + SM_BTV))[q];
                float4 r4;
                r4.x = (y[4 * q + 0] - mu) * inv * g4.x + t4.x;
                r4.y = (y[4 * q + 1] - mu) * inv * g4.y + t4.y;
                r4.z = (y[4 * q + 2] - mu) * inv * g4.z + t4.z;
                r4.w = (y[4 * q + 3] - mu) * inv * g4.w + t4.w;
                o[q] = r4;
            }
        }
        WG_BAR(wg);
    }
#endif
}

// ---------------------------------------------------------------------------
extern "C" void kernel_launch(void* const* d_in, const int* in_sizes, int n_in,
                              void* d_out, int out_size) {
    const float* ef   = (const float*)d_in[0];
    const float* nf   = (const float*)d_in[1];
    const void*  eidx = (const void*)d_in[2];
    const float* rbf  = (const float*)d_in[3];
    const float* W1   = (const float*)d_in[4];
    const float* b1   = (const float*)d_in[5];
    const float* W2   = (const float*)d_in[6];
    const float* b2   = (const float*)d_in[7];
    const float* W3   = (const float*)d_in[8];
    const float* b3   = (const float*)d_in[9];
    const float* gam  = (const float*)d_in[10];
    const float* bet  = (const float*)d_in[11];
    float* out = (float*)d_out;

    int E = in_sizes[0] / 64;
    int N = in_sizes[1] / 64;
    if (N > N_NODES_MAX) N = N_NODES_MAX;

    detect_idx_kernel<<<1, 1>>>((const unsigned int*)eidx);
    prep_w_kernel<<<32, 256>>>(W1, W2, W3);
    node_proj_kernel<<<(N + 15) / 16, 256>>>(nf, W1, N);

    int ntiles = (E + TILE - 1) / TILE;
    int grid = 148;
    if (grid > (ntiles + 2) / 3) grid = (ntiles + 2) / 3;
    if (grid < 1) grid = 1;
    cudaFuncSetAttribute(edge_tc_kernel,
                         cudaFuncAttributeMaxDynamicSharedMemorySize, SMEM_BYTES);
    edge_tc_kernel<<<grid, 384, SMEM_BYTES>>>(
        ef, eidx, rbf, W1, W2, W3, b1, b2, b3, gam, bet, out, E, ntiles);
}